// round 1
// baseline (speedup 1.0000x reference)
#include <cuda_runtime.h>
#include <math.h>
#include <stdint.h>

// ---------------- problem constants ----------------
#define NB    2048            // batch
#define NPIX1 256             // 16*16 after conv1
#define C1    128             // conv1 out channels
#define C2    256             // conv2 out channels (= D)
#define SPIX  64              // 8*8 after conv2
#define NROWS (NB*SPIX)       // 131072 VQ rows
#define KMAX  1024            // max concat codebook size
#define CH    16384           // classifier input dim (256*64)
#define HID   512

// ---------------- scratch (static device globals; no allocation) ----------------
__device__ float g_relu1[(size_t)NB * C1 * NPIX1];   // 268 MB
__device__ float g_fea  [(size_t)NB * C2 * SPIX];    // 134 MB
__device__ float g_qfea [(size_t)NB * C2 * SPIX];    // 134 MB
__device__ float g_h1   [(size_t)NB * HID];          // 4 MB
__device__ int   g_bi   [NROWS];
__device__ int   g_counts[KMAX];
__device__ float g_cn2  [KMAX];
__device__ float g_lossSum;

// ---------------- zero stats ----------------
__global__ void zero_stats_kernel() {
    int t = threadIdx.x;
    if (t < KMAX) g_counts[t] = 0;
    if (t == 0)   g_lossSum = 0.f;
}

// ---------------- conv1: 3->128, k4 s2 p1, 32x32 -> 16x16, relu ----------------
__global__ void conv1_kernel(const float* __restrict__ x,
                             const float* __restrict__ w1,
                             const float* __restrict__ b1) {
    __shared__ float sIn[3 * 32 * 32];
    __shared__ float sW [128 * 48];
    __shared__ float sB [128];
    int n = blockIdx.x, tid = threadIdx.x;
    for (int i = tid; i < 3072; i += 256) sIn[i] = x[(size_t)n * 3072 + i];
    for (int i = tid; i < 6144; i += 256) sW[i]  = w1[i];
    if (tid < 128) sB[tid] = b1[tid];
    __syncthreads();

    int oh = tid >> 4, ow = tid & 15;
    float a[48];
#pragma unroll
    for (int ci = 0; ci < 3; ci++)
#pragma unroll
        for (int kh = 0; kh < 4; kh++)
#pragma unroll
            for (int kw = 0; kw < 4; kw++) {
                int ih = 2 * oh - 1 + kh, iw = 2 * ow - 1 + kw;
                bool v = (ih >= 0 && ih < 32 && iw >= 0 && iw < 32);
                a[ci * 16 + kh * 4 + kw] = v ? sIn[ci * 1024 + ih * 32 + iw] : 0.f;
            }
    float* outp = g_relu1 + (size_t)n * (C1 * NPIX1) + tid;
    for (int oc = 0; oc < 128; oc++) {
        float acc = sB[oc];
#pragma unroll
        for (int t = 0; t < 48; t++) acc += a[t] * sW[oc * 48 + t];
        outp[(size_t)oc * 256] = fmaxf(acc, 0.f);
    }
}

// ---------------- conv2: 128->256, k4 s2 p1, 16x16 -> 8x8, relu ---------------
// implicit GEMM: per block (image n, 64-oc tile), K = 128ci*16tap, 4x4 reg tile
__global__ void conv2_kernel(const float* __restrict__ w2,
                             const float* __restrict__ b2) {
    __shared__ __align__(16) float sW[128 * 68];  // [ciL*16+tap][68]: oc
    __shared__ float sIn[2048];                   // [ciL][256 pix]
    int n   = blockIdx.y;
    int ocT = blockIdx.x * 64;
    int tid = threadIdx.x;
    int tx = tid & 15, ty = tid >> 4;

    float acc[4][4];
#pragma unroll
    for (int i = 0; i < 4; i++)
#pragma unroll
        for (int j = 0; j < 4; j++) acc[i][j] = 0.f;

    int sp[4], ohv[4], owv[4];
#pragma unroll
    for (int i = 0; i < 4; i++) { sp[i] = tx + 16 * i; ohv[i] = sp[i] >> 3; owv[i] = sp[i] & 7; }

    const float* gin = g_relu1 + (size_t)n * (C1 * NPIX1);

    for (int kc = 0; kc < 16; kc++) {
        __syncthreads();
#pragma unroll
        for (int r = 0; r < 8; r++) sIn[tid + 256 * r] = gin[(size_t)kc * 2048 + tid + 256 * r];
#pragma unroll
        for (int r = 0; r < 32; r++) {
            int L = tid + 256 * r;
            int oc = L >> 7, rem = L & 127;
            sW[rem * 68 + oc] = w2[(size_t)(ocT + oc) * 2048 + kc * 128 + rem];
        }
        __syncthreads();

#pragma unroll
        for (int kh = 0; kh < 4; kh++)
#pragma unroll
            for (int kw = 0; kw < 4; kw++) {
                int tap = kh * 4 + kw;
                int aidx[4]; bool av[4];
#pragma unroll
                for (int i = 0; i < 4; i++) {
                    int ih = 2 * ohv[i] - 1 + kh, iw = 2 * owv[i] - 1 + kw;
                    av[i]  = (ih >= 0 && ih < 16 && iw >= 0 && iw < 16);
                    aidx[i] = ih * 16 + iw;
                }
#pragma unroll
                for (int ci = 0; ci < 8; ci++) {
                    float4 w4 = *(const float4*)&sW[(ci * 16 + tap) * 68 + ty * 4];
                    float aa[4];
#pragma unroll
                    for (int i = 0; i < 4; i++) aa[i] = av[i] ? sIn[ci * 256 + aidx[i]] : 0.f;
#pragma unroll
                    for (int i = 0; i < 4; i++) {
                        acc[i][0] += aa[i] * w4.x;
                        acc[i][1] += aa[i] * w4.y;
                        acc[i][2] += aa[i] * w4.z;
                        acc[i][3] += aa[i] * w4.w;
                    }
                }
            }
    }

#pragma unroll
    for (int j = 0; j < 4; j++) {
        int oc = ocT + ty * 4 + j;
        float bb = b2[oc];
#pragma unroll
        for (int i = 0; i < 4; i++)
            g_fea[(size_t)n * CH + (size_t)oc * 64 + sp[i]] = fmaxf(acc[i][j] + bb, 0.f);
    }
}

// ---------------- code norms ----------------
__global__ void cn2_kernel(const float* __restrict__ cb0, const float* __restrict__ cb1,
                           const float* __restrict__ cb2, const int* __restrict__ idxp) {
    int j = blockIdx.x * 256 + threadIdx.x;
    int idx = *idxp;
    int Kc = (idx == 0) ? 512 : 1024;
    if (j >= KMAX) return;
    if (j < Kc) {
        const float* cbh = (idx == 1) ? cb1 : cb2;
        const float* cp = (j < 512) ? (cb0 + (size_t)j * 256) : (cbh + (size_t)(j - 512) * 256);
        float s = 0.f;
        for (int d = 0; d < 256; d++) { float v = cp[d]; s += v * v; }
        g_cn2[j] = s;
    } else g_cn2[j] = 0.f;
}

// ---------------- VQ: argmax(f.c - 0.5*||c||^2) per row ----------------
__global__ void vq_kernel(const float* __restrict__ cb0, const float* __restrict__ cb1,
                          const float* __restrict__ cb2, const int* __restrict__ idxp) {
    __shared__ float fS[32 * 65];
    __shared__ float cS[32 * 65];
    __shared__ float cns[64];
    __shared__ float redS[64 * 16];
    __shared__ int   redI[64 * 16];

    int n = blockIdx.x, tid = threadIdx.x;
    int tx = tid & 15, ty = tid >> 4;
    int idx = *idxp;
    int Kc = (idx == 0) ? 512 : 1024;
    const float* cbh = (idx == 1) ? cb1 : cb2;
    const float* feaN = g_fea + (size_t)n * CH;

    float bestS[4] = {-1e30f, -1e30f, -1e30f, -1e30f};
    int   bestI[4] = {0, 0, 0, 0};

    int T = Kc >> 6;
    for (int ct = 0; ct < T; ct++) {
        __syncthreads();            // protect cns from previous tile's readers
        int cbase = ct * 64;
        const float* cp = (cbase < 512) ? (cb0 + (size_t)cbase * 256)
                                        : (cbh + (size_t)(cbase - 512) * 256);
        if (tid < 64) cns[tid] = g_cn2[cbase + tid];

        float acc[4][4];
#pragma unroll
        for (int i = 0; i < 4; i++)
#pragma unroll
            for (int j = 0; j < 4; j++) acc[i][j] = 0.f;

        for (int kc = 0; kc < 8; kc++) {
            __syncthreads();
#pragma unroll
            for (int r = 0; r < 8; r++) {
                int L = tid + 256 * r;
                int d = L >> 6, s = L & 63;
                fS[d * 65 + s] = feaN[(size_t)(kc * 32 + d) * 64 + s];
                int j = L >> 5, dd = L & 31;
                cS[dd * 65 + j] = cp[(size_t)j * 256 + kc * 32 + dd];
            }
            __syncthreads();
#pragma unroll
            for (int d = 0; d < 32; d++) {
                float aa[4], cc[4];
#pragma unroll
                for (int i = 0; i < 4; i++) aa[i] = fS[d * 65 + tx + 16 * i];
#pragma unroll
                for (int j = 0; j < 4; j++) cc[j] = cS[d * 65 + ty * 4 + j];
#pragma unroll
                for (int i = 0; i < 4; i++)
#pragma unroll
                    for (int j = 0; j < 4; j++) acc[i][j] += aa[i] * cc[j];
            }
        }
#pragma unroll
        for (int i = 0; i < 4; i++)
#pragma unroll
            for (int j = 0; j < 4; j++) {
                float sc = acc[i][j] - 0.5f * cns[ty * 4 + j];
                if (sc > bestS[i]) { bestS[i] = sc; bestI[i] = cbase + ty * 4 + j; }
            }
    }

    __syncthreads();
#pragma unroll
    for (int i = 0; i < 4; i++) {
        redS[(tx + 16 * i) * 16 + ty] = bestS[i];
        redI[(tx + 16 * i) * 16 + ty] = bestI[i];
    }
    __syncthreads();
    if (tid < 64) {
        float bs = redS[tid * 16]; int bi = redI[tid * 16];
        for (int t = 1; t < 16; t++) {
            float s = redS[tid * 16 + t]; int ii = redI[tid * 16 + t];
            if (s > bs || (s == bs && ii < bi)) { bs = s; bi = ii; }
        }
        g_bi[n * 64 + tid] = bi;
    }
}

// ---------------- gather quantized + histogram + loss sum ----------------
__global__ void gather_kernel(const float* __restrict__ cb0, const float* __restrict__ cb1,
                              const float* __restrict__ cb2, const int* __restrict__ idxp) {
    __shared__ int sbi[64];
    __shared__ float wsum[8];
    int n = blockIdx.x, tid = threadIdx.x;
    int idx = *idxp;
    const float* cbh = (idx == 1) ? cb1 : cb2;
    if (tid < 64) {
        int b = g_bi[n * 64 + tid];
        sbi[tid] = b;
        atomicAdd(&g_counts[b], 1);
    }
    __syncthreads();
    const float* feaN = g_fea  + (size_t)n * CH;
    float*       qN   = g_qfea + (size_t)n * CH;
    float local = 0.f;
    for (int e = tid; e < CH; e += 256) {
        int d = e >> 6, s = e & 63;
        int b = sbi[s];
        float q = (b < 512) ? cb0[(size_t)b * 256 + d] : cbh[(size_t)(b - 512) * 256 + d];
        float f = feaN[e];
        float df = q - f;
        local += df * df;
        qN[e] = q;
    }
#pragma unroll
    for (int o = 16; o; o >>= 1) local += __shfl_xor_sync(0xffffffffu, local, o);
    if ((tid & 31) == 0) wsum[tid >> 5] = local;
    __syncthreads();
    if (tid == 0) {
        float t = 0.f;
        for (int w = 0; w < 8; w++) t += wsum[w];
        atomicAdd(&g_lossSum, t);
    }
}

// ---------------- fc1: (2048 x 16384) @ (16384 x 512) + exact gelu ----------------
__global__ void fc1_kernel(const float* __restrict__ fc1w, const float* __restrict__ fc1b) {
    __shared__ float aS[32 * 65];
    __shared__ float wS[32 * 65];
    int nT = blockIdx.y * 64, oT = blockIdx.x * 64;
    int tid = threadIdx.x;
    int tx = tid & 15, ty = tid >> 4;

    float acc[4][4];  // [jn][io]
#pragma unroll
    for (int i = 0; i < 4; i++)
#pragma unroll
        for (int j = 0; j < 4; j++) acc[i][j] = 0.f;

    for (int k0 = 0; k0 < CH; k0 += 32) {
        __syncthreads();
#pragma unroll
        for (int r = 0; r < 8; r++) {
            int L = tid + 256 * r;
            int rr = L >> 5, kk = L & 31;
            aS[kk * 65 + rr] = g_qfea[(size_t)(nT + rr) * CH + k0 + kk];
            wS[kk * 65 + rr] = fc1w[(size_t)(oT + rr) * CH + k0 + kk];
        }
        __syncthreads();
#pragma unroll
        for (int kk = 0; kk < 32; kk++) {
            float av[4], wv[4];
#pragma unroll
            for (int jn = 0; jn < 4; jn++) av[jn] = aS[kk * 65 + ty * 4 + jn];
#pragma unroll
            for (int io = 0; io < 4; io++) wv[io] = wS[kk * 65 + tx + 16 * io];
#pragma unroll
            for (int jn = 0; jn < 4; jn++)
#pragma unroll
                for (int io = 0; io < 4; io++) acc[jn][io] += av[jn] * wv[io];
        }
    }
#pragma unroll
    for (int jn = 0; jn < 4; jn++) {
        int nn = nT + ty * 4 + jn;
#pragma unroll
        for (int io = 0; io < 4; io++) {
            int oo = oT + tx + 16 * io;
            float v = acc[jn][io] + fc1b[oo];
            float g = 0.5f * v * (1.0f + erff(v * 0.70710678118654752f));
            g_h1[(size_t)nn * HID + oo] = g;
        }
    }
}

// ---------------- fc2: (2048 x 512) @ (512 x 10) ----------------
__global__ void fc2_kernel(const float* __restrict__ w, const float* __restrict__ b,
                           float* __restrict__ out) {
    int gwarp = (blockIdx.x * 256 + threadIdx.x) >> 5;
    int lane = threadIdx.x & 31;
    if (gwarp >= NB) return;
    float acc[10];
#pragma unroll
    for (int o = 0; o < 10; o++) acc[o] = 0.f;
    const float* hrow = g_h1 + (size_t)gwarp * HID;
    for (int k = lane; k < HID; k += 32) {
        float h = hrow[k];
#pragma unroll
        for (int o = 0; o < 10; o++) acc[o] += h * w[o * HID + k];
    }
#pragma unroll
    for (int o = 0; o < 10; o++)
#pragma unroll
        for (int off = 16; off; off >>= 1) acc[o] += __shfl_xor_sync(0xffffffffu, acc[o], off);
    if (lane == 0) {
#pragma unroll
        for (int o = 0; o < 10; o++) out[(size_t)gwarp * 10 + o] = acc[o] + b[o];
    }
}

// ---------------- finalize: loss + perplexity ----------------
__global__ void finalize_kernel(float* __restrict__ out) {
    __shared__ float wsum[8];
    int tid = threadIdx.x;
    float local = 0.f;
    for (int k = tid; k < KMAX; k += 256) {
        float p = (float)g_counts[k] * (1.0f / 131072.0f);
        local += p * logf(p + 1e-10f);
    }
#pragma unroll
    for (int o = 16; o; o >>= 1) local += __shfl_xor_sync(0xffffffffu, local, o);
    if ((tid & 31) == 0) wsum[tid >> 5] = local;
    __syncthreads();
    if (tid == 0) {
        float t = 0.f;
        for (int w = 0; w < 8; w++) t += wsum[w];
        out[20480] = 1.25f * g_lossSum * (1.0f / 33554432.0f);
        out[20481] = expf(-t);
    }
}

// ---------------- launch ----------------
extern "C" void kernel_launch(void* const* d_in, const int* in_sizes, int n_in,
                              void* d_out, int out_size) {
    const float* x    = (const float*)d_in[0];
    const int*   idxp = (const int*)  d_in[1];
    const float* w1   = (const float*)d_in[2];
    const float* b1   = (const float*)d_in[3];
    const float* w2   = (const float*)d_in[4];
    const float* b2   = (const float*)d_in[5];
    const float* cb0  = (const float*)d_in[6];
    const float* cb1  = (const float*)d_in[7];
    const float* cb2  = (const float*)d_in[8];
    const float* f1w  = (const float*)d_in[9];
    const float* f1b  = (const float*)d_in[10];
    const float* f2w  = (const float*)d_in[11];
    const float* f2b  = (const float*)d_in[12];
    float* out = (float*)d_out;

    zero_stats_kernel<<<1, 1024>>>();
    conv1_kernel<<<NB, 256>>>(x, w1, b1);
    conv2_kernel<<<dim3(4, NB), 256>>>(w2, b2);
    cn2_kernel<<<4, 256>>>(cb0, cb1, cb2, idxp);
    vq_kernel<<<NB, 256>>>(cb0, cb1, cb2, idxp);
    gather_kernel<<<NB, 256>>>(cb0, cb1, cb2, idxp);
    fc1_kernel<<<dim3(8, 32), 256>>>(f1w, f1b);
    fc2_kernel<<<NB / 8, 256>>>(f2w, f2b, out);
    finalize_kernel<<<1, 256>>>(out);
}

// round 6
// speedup vs baseline: 1.0184x; 1.0184x over previous
#include <cuda_runtime.h>
#include <cuda_bf16.h>
#include <math.h>
#include <stdint.h>

// ---------------- problem constants ----------------
#define NB    2048
#define NPIX1 256
#define C1    128
#define C2    256
#define SPIX  64
#define NROWS (NB*SPIX)
#define KMAX  1024
#define CH    16384
#define HID   512

// ---------------- scratch ----------------
__device__ float         g_relu1[(size_t)NB * C1 * NPIX1];
__device__ float         g_fea  [(size_t)NB * C2 * SPIX];    // col-major per image: [oc][s]
__device__ int           g_bi   [NROWS];
__device__ float         g_cn2  [KMAX];
__device__ __nv_bfloat16 g_qh[(size_t)NB * CH], g_ql[(size_t)NB * CH];  // rows=(n*64+s), col=oc
__device__ __nv_bfloat16 g_f1wh[(size_t)HID * CH], g_f1wl[(size_t)HID * CH];
__device__ float         g_h1   [(size_t)NB * HID];
__device__ int           g_counts[KMAX];
__device__ float         g_lossSum;

// ---------------- helpers ----------------
__device__ __forceinline__ uint32_t s2u(const void* p) {
    return (uint32_t)__cvta_generic_to_shared(p);
}
__device__ __forceinline__ void cpasync16(uint32_t s, const void* g) {
    asm volatile("cp.async.cg.shared.global [%0], [%1], 16;" :: "r"(s), "l"(g));
}
__device__ __forceinline__ void ldsm4(uint32_t* r, uint32_t s) {
    asm volatile("ldmatrix.sync.aligned.m8n8.x4.shared.b16 {%0,%1,%2,%3}, [%4];"
                 : "=r"(r[0]), "=r"(r[1]), "=r"(r[2]), "=r"(r[3]) : "r"(s));
}
__device__ __forceinline__ void mma16816(float* c, const uint32_t* a, const uint32_t* b) {
    asm volatile("mma.sync.aligned.m16n8k16.row.col.f32.bf16.bf16.f32 "
                 "{%0,%1,%2,%3}, {%4,%5,%6,%7}, {%8,%9}, {%0,%1,%2,%3};"
                 : "+f"(c[0]), "+f"(c[1]), "+f"(c[2]), "+f"(c[3])
                 : "r"(a[0]), "r"(a[1]), "r"(a[2]), "r"(a[3]), "r"(b[0]), "r"(b[1]));
}
__device__ __forceinline__ void split2(float v, __nv_bfloat16& h, __nv_bfloat16& l) {
    h = __float2bfloat16(v);
    l = __float2bfloat16(v - __bfloat162float(h));
}

// ---------------- zero stats ----------------
__global__ void zero_stats_kernel() {
    int t = threadIdx.x;
    if (t < KMAX) g_counts[t] = 0;
    if (t == 0)   g_lossSum = 0.f;
}

// ---------------- conv1 (R1 verbatim) ----------------
__global__ void conv1_kernel(const float* __restrict__ x,
                             const float* __restrict__ w1,
                             const float* __restrict__ b1) {
    __shared__ float sIn[3 * 32 * 32];
    __shared__ float sW [128 * 48];
    __shared__ float sB [128];
    int n = blockIdx.x, tid = threadIdx.x;
    for (int i = tid; i < 3072; i += 256) sIn[i] = x[(size_t)n * 3072 + i];
    for (int i = tid; i < 6144; i += 256) sW[i]  = w1[i];
    if (tid < 128) sB[tid] = b1[tid];
    __syncthreads();

    int oh = tid >> 4, ow = tid & 15;
    float a[48];
#pragma unroll
    for (int ci = 0; ci < 3; ci++)
#pragma unroll
        for (int kh = 0; kh < 4; kh++)
#pragma unroll
            for (int kw = 0; kw < 4; kw++) {
                int ih = 2 * oh - 1 + kh, iw = 2 * ow - 1 + kw;
                bool v = (ih >= 0 && ih < 32 && iw >= 0 && iw < 32);
                a[ci * 16 + kh * 4 + kw] = v ? sIn[ci * 1024 + ih * 32 + iw] : 0.f;
            }
    float* outp = g_relu1 + (size_t)n * (C1 * NPIX1) + tid;
    for (int oc = 0; oc < 128; oc++) {
        float acc = sB[oc];
#pragma unroll
        for (int t = 0; t < 48; t++) acc += a[t] * sW[oc * 48 + t];
        outp[(size_t)oc * 256] = fmaxf(acc, 0.f);
    }
}

// ---------------- conv2: R1 FMA order, zero-padded smem (bit-identical) -------
__global__ void conv2_kernel(const float* __restrict__ w2,
                             const float* __restrict__ b2) {
    __shared__ __align__(16) float sW[128 * 68];  // [ciL*16+tap][68]: oc
    __shared__ float sInP[8 * 324];               // [ciL][18*18 zero-padded]
    int n   = blockIdx.y;
    int ocT = blockIdx.x * 64;
    int tid = threadIdx.x;
    int tx = tid & 15, ty = tid >> 4;

    float acc[4][4];
#pragma unroll
    for (int i = 0; i < 4; i++)
#pragma unroll
        for (int j = 0; j < 4; j++) acc[i][j] = 0.f;

    int sp[4], base[4];
#pragma unroll
    for (int i = 0; i < 4; i++) {
        sp[i] = tx + 16 * i;
        int oh = sp[i] >> 3, ow = sp[i] & 7;
        base[i] = (2 * oh) * 18 + 2 * ow;   // (2oh-1+kh)+1 row, (2ow-1+kw)+1 col
    }

    const float* gin = g_relu1 + (size_t)n * (C1 * NPIX1);

    // zero borders once; interior overwritten every kc
    for (int i = tid; i < 2592; i += 256) sInP[i] = 0.f;

    for (int kc = 0; kc < 16; kc++) {
        __syncthreads();
#pragma unroll
        for (int r = 0; r < 8; r++) {
            int idx = tid + 256 * r;
            int ci = idx >> 8, p = idx & 255;
            sInP[ci * 324 + ((p >> 4) + 1) * 18 + (p & 15) + 1] = gin[(size_t)kc * 2048 + idx];
        }
#pragma unroll
        for (int r = 0; r < 32; r++) {
            int L = tid + 256 * r;
            int oc = L >> 7, rem = L & 127;
            sW[rem * 68 + oc] = w2[(size_t)(ocT + oc) * 2048 + kc * 128 + rem];
        }
        __syncthreads();

#pragma unroll
        for (int kh = 0; kh < 4; kh++)
#pragma unroll
            for (int kw = 0; kw < 4; kw++) {
                int tap = kh * 4 + kw;
                int off = kh * 18 + kw;
#pragma unroll
                for (int ci = 0; ci < 8; ci++) {
                    float4 w4 = *(const float4*)&sW[(ci * 16 + tap) * 68 + ty * 4];
                    float aa[4];
#pragma unroll
                    for (int i = 0; i < 4; i++) aa[i] = sInP[ci * 324 + base[i] + off];
#pragma unroll
                    for (int i = 0; i < 4; i++) {
                        acc[i][0] += aa[i] * w4.x;
                        acc[i][1] += aa[i] * w4.y;
                        acc[i][2] += aa[i] * w4.z;
                        acc[i][3] += aa[i] * w4.w;
                    }
                }
            }
    }

#pragma unroll
    for (int j = 0; j < 4; j++) {
        int oc = ocT + ty * 4 + j;
        float bb = b2[oc];
#pragma unroll
        for (int i = 0; i < 4; i++)
            g_fea[(size_t)n * CH + (size_t)oc * 64 + sp[i]] = fmaxf(acc[i][j] + bb, 0.f);
    }
}

// ---------------- code norms (R1 verbatim) ----------------
__global__ void cn2_kernel(const float* __restrict__ cb0, const float* __restrict__ cb1,
                           const float* __restrict__ cb2, const int* __restrict__ idxp) {
    int j = blockIdx.x * 256 + threadIdx.x;
    int idx = *idxp;
    int Kc = (idx == 0) ? 512 : 1024;
    if (j >= KMAX) return;
    if (j < Kc) {
        const float* cbh = (idx == 1) ? cb1 : cb2;
        const float* cp = (j < 512) ? (cb0 + (size_t)j * 256) : (cbh + (size_t)(j - 512) * 256);
        float s = 0.f;
        for (int d = 0; d < 256; d++) { float v = cp[d]; s += v * v; }
        g_cn2[j] = s;
    } else g_cn2[j] = 0.f;
}

// ---------------- VQ (R1 verbatim) ----------------
__global__ void vq_kernel(const float* __restrict__ cb0, const float* __restrict__ cb1,
                          const float* __restrict__ cb2, const int* __restrict__ idxp) {
    __shared__ float fS[32 * 65];
    __shared__ float cS[32 * 65];
    __shared__ float cns[64];
    __shared__ float redS[64 * 16];
    __shared__ int   redI[64 * 16];

    int n = blockIdx.x, tid = threadIdx.x;
    int tx = tid & 15, ty = tid >> 4;
    int idx = *idxp;
    int Kc = (idx == 0) ? 512 : 1024;
    const float* cbh = (idx == 1) ? cb1 : cb2;
    const float* feaN = g_fea + (size_t)n * CH;

    float bestS[4] = {-1e30f, -1e30f, -1e30f, -1e30f};
    int   bestI[4] = {0, 0, 0, 0};

    int T = Kc >> 6;
    for (int ct = 0; ct < T; ct++) {
        __syncthreads();
        int cbase = ct * 64;
        const float* cp = (cbase < 512) ? (cb0 + (size_t)cbase * 256)
                                        : (cbh + (size_t)(cbase - 512) * 256);
        if (tid < 64) cns[tid] = g_cn2[cbase + tid];

        float acc[4][4];
#pragma unroll
        for (int i = 0; i < 4; i++)
#pragma unroll
            for (int j = 0; j < 4; j++) acc[i][j] = 0.f;

        for (int kc = 0; kc < 8; kc++) {
            __syncthreads();
#pragma unroll
            for (int r = 0; r < 8; r++) {
                int L = tid + 256 * r;
                int d = L >> 6, s = L & 63;
                fS[d * 65 + s] = feaN[(size_t)(kc * 32 + d) * 64 + s];
                int j = L >> 5, dd = L & 31;
                cS[dd * 65 + j] = cp[(size_t)j * 256 + kc * 32 + dd];
            }
            __syncthreads();
#pragma unroll
            for (int d = 0; d < 32; d++) {
                float aa[4], cc[4];
#pragma unroll
                for (int i = 0; i < 4; i++) aa[i] = fS[d * 65 + tx + 16 * i];
#pragma unroll
                for (int j = 0; j < 4; j++) cc[j] = cS[d * 65 + ty * 4 + j];
#pragma unroll
                for (int i = 0; i < 4; i++)
#pragma unroll
                    for (int j = 0; j < 4; j++) acc[i][j] += aa[i] * cc[j];
            }
        }
#pragma unroll
        for (int i = 0; i < 4; i++)
#pragma unroll
            for (int j = 0; j < 4; j++) {
                float sc = acc[i][j] - 0.5f * cns[ty * 4 + j];
                if (sc > bestS[i]) { bestS[i] = sc; bestI[i] = cbase + ty * 4 + j; }
            }
    }

    __syncthreads();
#pragma unroll
    for (int i = 0; i < 4; i++) {
        redS[(tx + 16 * i) * 16 + ty] = bestS[i];
        redI[(tx + 16 * i) * 16 + ty] = bestI[i];
    }
    __syncthreads();
    if (tid < 64) {
        float bs = redS[tid * 16]; int bi = redI[tid * 16];
        for (int t = 1; t < 16; t++) {
            float s = redS[tid * 16 + t]; int ii = redI[tid * 16 + t];
            if (s > bs || (s == bs && ii < bi)) { bs = s; bi = ii; }
        }
        g_bi[n * 64 + tid] = bi;
    }
}

// ---------------- gather: R1 loss math + qh/ql split writes -------------------
__global__ void gather_kernel(const float* __restrict__ cb0, const float* __restrict__ cb1,
                              const float* __restrict__ cb2, const int* __restrict__ idxp) {
    __shared__ int sbi[64];
    __shared__ float wsum[8];
    int n = blockIdx.x, tid = threadIdx.x;
    int idx = *idxp;
    const float* cbh = (idx == 1) ? cb1 : cb2;
    if (tid < 64) {
        int b = g_bi[n * 64 + tid];
        sbi[tid] = b;
        atomicAdd(&g_counts[b], 1);
    }
    __syncthreads();
    const float* feaN = g_fea + (size_t)n * CH;
    float local = 0.f;
    for (int e = tid; e < CH; e += 256) {
        int d = e >> 6, s = e & 63;
        int b = sbi[s];
        float q = (b < 512) ? cb0[(size_t)b * 256 + d] : cbh[(size_t)(b - 512) * 256 + d];
        float f = feaN[e];
        float df = q - f;
        local += df * df;
        __nv_bfloat16 qh, ql;
        split2(q, qh, ql);
        size_t rr = ((size_t)n * 64 + s) * 256 + d;
        g_qh[rr] = qh;
        g_ql[rr] = ql;
    }
#pragma unroll
    for (int o = 16; o; o >>= 1) local += __shfl_xor_sync(0xffffffffu, local, o);
    if ((tid & 31) == 0) wsum[tid >> 5] = local;
    __syncthreads();
    if (tid == 0) {
        float t = 0.f;
        for (int w = 0; w < 8; w++) t += wsum[w];
        atomicAdd(&g_lossSum, t);
    }
}

// ---------------- prep: fc1 weight permute (k'=s*256+oc) + split --------------
__global__ void prep_f1w_kernel(const float* __restrict__ f1w) {
    int gid = blockIdx.x * 256 + threadIdx.x;   // 512*16384
    int h = gid >> 14, kp = gid & 16383;
    int s = kp >> 8, oc = kp & 255;
    float v = f1w[(size_t)h * CH + oc * 64 + s];
    split2(v, g_f1wh[gid], g_f1wl[gid]);
}

// ---------------- fc1 TC GEMM (bf16x3): h1 = gelu(Q @ W^T + b) -----------------
// A = g_qh/g_ql rows as 2048x16384 (row n = image), B = permuted W 512x16384
__global__ void __launch_bounds__(256) fc1_tc_kernel(const float* __restrict__ f1b) {
    constexpr int BM = 128, BN = 64, LDK = 40, K = CH;
    constexpr int BOFF = 2 * 2 * BM * LDK;      // A region elements

    const __nv_bfloat16* Ag[2] = {g_qh, g_ql};
    const __nv_bfloat16* Bg[2] = {g_f1wh, g_f1wl};

    extern __shared__ __nv_bfloat16 sm[];

    const int tid = threadIdx.x;
    const int warp = tid >> 5, lane = tid & 31;
    const int wm = warp & 1, wn = warp >> 1;
    const size_t m0 = (size_t)blockIdx.y * BM;
    const int n0 = blockIdx.x * BN;

    float acc[4][2][4];
#pragma unroll
    for (int i = 0; i < 4; i++)
#pragma unroll
        for (int j = 0; j < 2; j++)
#pragma unroll
            for (int q = 0; q < 4; q++) acc[i][j][q] = 0.f;

    auto issue = [&](int kt) {
        int st = kt & 1;
        size_t kb = (size_t)kt * 32;
#pragma unroll
        for (int p = 0; p < 2; p++) {
            for (int i = tid; i < BM * 4; i += 256) {
                int r = i >> 2, c = (i & 3) * 8;
                cpasync16(s2u(&sm[((p * 2 + st) * BM + r) * LDK + c]),
                          Ag[p] + (m0 + r) * K + kb + c);
            }
            for (int i = tid; i < BN * 4; i += 256) {
                int r = i >> 2, c = (i & 3) * 8;
                cpasync16(s2u(&sm[BOFF + ((p * 2 + st) * BN + r) * LDK + c]),
                          Bg[p] + (size_t)(n0 + r) * K + kb + c);
            }
        }
        asm volatile("cp.async.commit_group;");
    };

    constexpr int NK = K / 32;   // 512
    issue(0);
    for (int kt = 0; kt < NK; kt++) {
        if (kt + 1 < NK) {
            issue(kt + 1);
            asm volatile("cp.async.wait_group 1;");
        } else {
            asm volatile("cp.async.wait_group 0;");
        }
        __syncthreads();
        int st = kt & 1;
#pragma unroll
        for (int ks = 0; ks < 2; ks++) {
            int arow = wm * 64 + (lane & 15);
            int acol = ks * 16 + (lane >> 4) * 8;
            int brow = wn * 16 + (lane & 7) + ((lane >> 4) << 3);
            int bcol = ks * 16 + ((lane >> 3) & 1) * 8;

            uint32_t a0[4][4], a1[4][4], b0[4], b1[4];
#pragma unroll
            for (int mi = 0; mi < 4; mi++) {
                ldsm4(a0[mi], s2u(&sm[((0 * 2 + st) * BM + arow + mi * 16) * LDK + acol]));
                ldsm4(a1[mi], s2u(&sm[((1 * 2 + st) * BM + arow + mi * 16) * LDK + acol]));
            }
            ldsm4(b0, s2u(&sm[BOFF + ((0 * 2 + st) * BN + brow) * LDK + bcol]));
            ldsm4(b1, s2u(&sm[BOFF + ((1 * 2 + st) * BN + brow) * LDK + bcol]));

#pragma unroll
            for (int mi = 0; mi < 4; mi++)
#pragma unroll
                for (int j = 0; j < 2; j++) {
                    mma16816(acc[mi][j], a0[mi], &b0[j * 2]);   // (0,0)
                    mma16816(acc[mi][j], a0[mi], &b1[j * 2]);   // (0,1)
                    mma16816(acc[mi][j], a1[mi], &b0[j * 2]);   // (1,0)
                }
        }
        __syncthreads();
    }

#pragma unroll
    for (int mi = 0; mi < 4; mi++)
#pragma unroll
        for (int j = 0; j < 2; j++) {
            size_t row = m0 + wm * 64 + mi * 16 + (lane >> 2);
            int col = n0 + wn * 16 + j * 8 + (lane & 3) * 2;
            float* c = acc[mi][j];
#pragma unroll
            for (int half = 0; half < 2; half++) {
                size_t r = row + half * 8;
                float a0v = c[half * 2 + 0] + __ldg(&f1b[col]);
                float a1v = c[half * 2 + 1] + __ldg(&f1b[col + 1]);
                float2 o;
                o.x = 0.5f * a0v * (1.f + erff(a0v * 0.70710678118654752f));
                o.y = 0.5f * a1v * (1.f + erff(a1v * 0.70710678118654752f));
                *reinterpret_cast<float2*>(&g_h1[r * HID + col]) = o;
            }
        }
}

// ---------------- fc2 (R1 verbatim) ----------------
__global__ void fc2_kernel(const float* __restrict__ w, const float* __restrict__ b,
                           float* __restrict__ out) {
    int gwarp = (blockIdx.x * 256 + threadIdx.x) >> 5;
    int lane = threadIdx.x & 31;
    if (gwarp >= NB) return;
    float acc[10];
#pragma unroll
    for (int o = 0; o < 10; o++) acc[o] = 0.f;
    const float* hrow = g_h1 + (size_t)gwarp * HID;
    for (int k = lane; k < HID; k += 32) {
        float h = hrow[k];
#pragma unroll
        for (int o = 0; o < 10; o++) acc[o] += h * w[o * HID + k];
    }
#pragma unroll
    for (int o = 0; o < 10; o++)
#pragma unroll
        for (int off = 16; off; off >>= 1) acc[o] += __shfl_xor_sync(0xffffffffu, acc[o], off);
    if (lane == 0) {
#pragma unroll
        for (int o = 0; o < 10; o++) out[(size_t)gwarp * 10 + o] = acc[o] + b[o];
    }
}

// ---------------- finalize (R1 verbatim) ----------------
__global__ void finalize_kernel(float* __restrict__ out) {
    __shared__ float wsum[8];
    int tid = threadIdx.x;
    float local = 0.f;
    for (int k = tid; k < KMAX; k += 256) {
        float p = (float)g_counts[k] * (1.0f / 131072.0f);
        local += p * logf(p + 1e-10f);
    }
#pragma unroll
    for (int o = 16; o; o >>= 1) local += __shfl_xor_sync(0xffffffffu, local, o);
    if ((tid & 31) == 0) wsum[tid >> 5] = local;
    __syncthreads();
    if (tid == 0) {
        float t = 0.f;
        for (int w = 0; w < 8; w++) t += wsum[w];
        out[20480] = 1.25f * g_lossSum * (1.0f / 33554432.0f);
        out[20481] = expf(-t);
    }
}

// ---------------- launch ----------------
extern "C" void kernel_launch(void* const* d_in, const int* in_sizes, int n_in,
                              void* d_out, int out_size) {
    const float* x    = (const float*)d_in[0];
    const int*   idxp = (const int*)  d_in[1];
    const float* w1   = (const float*)d_in[2];
    const float* b1   = (const float*)d_in[3];
    const float* w2   = (const float*)d_in[4];
    const float* b2   = (const float*)d_in[5];
    const float* cb0  = (const float*)d_in[6];
    const float* cb1  = (const float*)d_in[7];
    const float* cb2  = (const float*)d_in[8];
    const float* f1w  = (const float*)d_in[9];
    const float* f1b  = (const float*)d_in[10];
    const float* f2w  = (const float*)d_in[11];
    const float* f2b  = (const float*)d_in[12];
    float* out = (float*)d_out;

    constexpr int SMF = (2 * 2 * 128 + 2 * 2 * 64) * 40 * 2;  // 61440 B
    cudaFuncSetAttribute(fc1_tc_kernel, cudaFuncAttributeMaxDynamicSharedMemorySize, SMF);

    zero_stats_kernel<<<1, 1024>>>();
    prep_f1w_kernel<<<32768, 256>>>(f1w);
    conv1_kernel<<<NB, 256>>>(x, w1, b1);
    conv2_kernel<<<dim3(4, NB), 256>>>(w2, b2);
    cn2_kernel<<<4, 256>>>(cb0, cb1, cb2, idxp);
    vq_kernel<<<NB, 256>>>(cb0, cb1, cb2, idxp);
    gather_kernel<<<NB, 256>>>(cb0, cb1, cb2, idxp);
    fc1_tc_kernel<<<dim3(8, 16), 256, SMF>>>(f1b);
    fc2_kernel<<<NB / 8, 256>>>(f2w, f2b, out);
    finalize_kernel<<<1, 256>>>(out);
}

// round 7
// speedup vs baseline: 1.0343x; 1.0156x over previous
#include <cuda_runtime.h>
#include <cuda_bf16.h>
#include <math.h>
#include <stdint.h>

// ---------------- problem constants ----------------
#define NB    2048
#define NPIX1 256
#define C1    128
#define C2    256
#define SPIX  64
#define NROWS (NB*SPIX)
#define KMAX  1024
#define CH    16384
#define HID   512

// ---------------- scratch ----------------
__device__ float         g_relu1[(size_t)NB * C1 * NPIX1];
__device__ float         g_fea  [(size_t)NB * C2 * SPIX];    // col-major per image: [oc][s]
__device__ int           g_bi   [NROWS];
__device__ float         g_cn2  [KMAX];
__device__ __nv_bfloat16 g_qh[(size_t)NB * CH], g_ql[(size_t)NB * CH];  // row=(n), col=s*256+oc
__device__ __nv_bfloat16 g_f1wh[(size_t)HID * CH], g_f1wl[(size_t)HID * CH];
__device__ float         g_h1   [(size_t)NB * HID];
__device__ int           g_counts[KMAX];
__device__ float         g_lossSum;

// ---------------- helpers ----------------
__device__ __forceinline__ uint32_t s2u(const void* p) {
    return (uint32_t)__cvta_generic_to_shared(p);
}
__device__ __forceinline__ void cpasync16(uint32_t s, const void* g) {
    asm volatile("cp.async.cg.shared.global [%0], [%1], 16;" :: "r"(s), "l"(g));
}
__device__ __forceinline__ void ldsm4(uint32_t* r, uint32_t s) {
    asm volatile("ldmatrix.sync.aligned.m8n8.x4.shared.b16 {%0,%1,%2,%3}, [%4];"
                 : "=r"(r[0]), "=r"(r[1]), "=r"(r[2]), "=r"(r[3]) : "r"(s));
}
__device__ __forceinline__ void mma16816(float* c, const uint32_t* a, const uint32_t* b) {
    asm volatile("mma.sync.aligned.m16n8k16.row.col.f32.bf16.bf16.f32 "
                 "{%0,%1,%2,%3}, {%4,%5,%6,%7}, {%8,%9}, {%0,%1,%2,%3};"
                 : "+f"(c[0]), "+f"(c[1]), "+f"(c[2]), "+f"(c[3])
                 : "r"(a[0]), "r"(a[1]), "r"(a[2]), "r"(a[3]), "r"(b[0]), "r"(b[1]));
}
__device__ __forceinline__ void split2(float v, __nv_bfloat16& h, __nv_bfloat16& l) {
    h = __float2bfloat16(v);
    l = __float2bfloat16(v - __bfloat162float(h));
}
// packed f32x2 FMA: two independent IEEE-rn fp32 FMAs per instruction
__device__ __forceinline__ unsigned long long pk2(float x, float y) {
    unsigned long long r;
    asm("mov.b64 %0, {%1, %2};" : "=l"(r) : "f"(x), "f"(y));
    return r;
}
__device__ __forceinline__ float2 upk2(unsigned long long v) {
    float2 f;
    asm("mov.b64 {%0, %1}, %2;" : "=f"(f.x), "=f"(f.y) : "l"(v));
    return f;
}
#define FMA2(d, a, b) asm("fma.rn.f32x2 %0, %1, %2, %0;" : "+l"(d) : "l"(a), "l"(b))

// ---------------- zero stats ----------------
__global__ void zero_stats_kernel() {
    int t = threadIdx.x;
    if (t < KMAX) g_counts[t] = 0;
    if (t == 0)   g_lossSum = 0.f;
}

// ---------------- conv1 (R1 verbatim) ----------------
__global__ void conv1_kernel(const float* __restrict__ x,
                             const float* __restrict__ w1,
                             const float* __restrict__ b1) {
    __shared__ float sIn[3 * 32 * 32];
    __shared__ float sW [128 * 48];
    __shared__ float sB [128];
    int n = blockIdx.x, tid = threadIdx.x;
    for (int i = tid; i < 3072; i += 256) sIn[i] = x[(size_t)n * 3072 + i];
    for (int i = tid; i < 6144; i += 256) sW[i]  = w1[i];
    if (tid < 128) sB[tid] = b1[tid];
    __syncthreads();

    int oh = tid >> 4, ow = tid & 15;
    float a[48];
#pragma unroll
    for (int ci = 0; ci < 3; ci++)
#pragma unroll
        for (int kh = 0; kh < 4; kh++)
#pragma unroll
            for (int kw = 0; kw < 4; kw++) {
                int ih = 2 * oh - 1 + kh, iw = 2 * ow - 1 + kw;
                bool v = (ih >= 0 && ih < 32 && iw >= 0 && iw < 32);
                a[ci * 16 + kh * 4 + kw] = v ? sIn[ci * 1024 + ih * 32 + iw] : 0.f;
            }
    float* outp = g_relu1 + (size_t)n * (C1 * NPIX1) + tid;
    for (int oc = 0; oc < 128; oc++) {
        float acc = sB[oc];
#pragma unroll
        for (int t = 0; t < 48; t++) acc += a[t] * sW[oc * 48 + t];
        outp[(size_t)oc * 256] = fmaxf(acc, 0.f);
    }
}

// ---------------- conv2: R6 semantics, j-pairs packed into fma.rn.f32x2 -------
// per-output accumulation chain order identical to R6 -> bit-identical g_fea
__global__ void conv2_kernel(const float* __restrict__ w2,
                             const float* __restrict__ b2) {
    __shared__ __align__(16) float sW[128 * 68];  // [ciL*16+tap][68]: oc
    __shared__ float sInP[8 * 324];               // [ciL][18*18 zero-padded]
    int n   = blockIdx.y;
    int ocT = blockIdx.x * 64;
    int tid = threadIdx.x;
    int tx = tid & 15, ty = tid >> 4;

    unsigned long long acc2[4][2];
#pragma unroll
    for (int i = 0; i < 4; i++) { acc2[i][0] = 0ull; acc2[i][1] = 0ull; }

    int sp[4], base[4];
#pragma unroll
    for (int i = 0; i < 4; i++) {
        sp[i] = tx + 16 * i;
        int oh = sp[i] >> 3, ow = sp[i] & 7;
        base[i] = (2 * oh) * 18 + 2 * ow;
    }

    const float* gin = g_relu1 + (size_t)n * (C1 * NPIX1);

    for (int i = tid; i < 2592; i += 256) sInP[i] = 0.f;

    for (int kc = 0; kc < 16; kc++) {
        __syncthreads();
#pragma unroll
        for (int r = 0; r < 8; r++) {
            int idx = tid + 256 * r;
            int ci = idx >> 8, p = idx & 255;
            sInP[ci * 324 + ((p >> 4) + 1) * 18 + (p & 15) + 1] = gin[(size_t)kc * 2048 + idx];
        }
#pragma unroll
        for (int r = 0; r < 32; r++) {
            int L = tid + 256 * r;
            int oc = L >> 7, rem = L & 127;
            sW[rem * 68 + oc] = w2[(size_t)(ocT + oc) * 2048 + kc * 128 + rem];
        }
        __syncthreads();

#pragma unroll
        for (int kh = 0; kh < 4; kh++)
#pragma unroll
            for (int kw = 0; kw < 4; kw++) {
                int tap = kh * 4 + kw;
                int off = kh * 18 + kw;
#pragma unroll
                for (int ci = 0; ci < 8; ci++) {
                    // (ci*16+tap)*68 + ty*4 is a multiple of 4 floats -> 16B aligned
                    const ulonglong2 wv = *(const ulonglong2*)&sW[(ci * 16 + tap) * 68 + ty * 4];
#pragma unroll
                    for (int i = 0; i < 4; i++) {
                        float a = sInP[ci * 324 + base[i] + off];
                        unsigned long long a2 = pk2(a, a);
                        FMA2(acc2[i][0], a2, wv.x);
                        FMA2(acc2[i][1], a2, wv.y);
                    }
                }
            }
    }

#pragma unroll
    for (int i = 0; i < 4; i++) {
        float2 p01 = upk2(acc2[i][0]);
        float2 p23 = upk2(acc2[i][1]);
        float vj[4] = {p01.x, p01.y, p23.x, p23.y};
#pragma unroll
        for (int j = 0; j < 4; j++) {
            int oc = ocT + ty * 4 + j;
            g_fea[(size_t)n * CH + (size_t)oc * 64 + sp[i]] = fmaxf(vj[j] + b2[oc], 0.f);
        }
    }
}

// ---------------- code norms (R1 verbatim) ----------------
__global__ void cn2_kernel(const float* __restrict__ cb0, const float* __restrict__ cb1,
                           const float* __restrict__ cb2, const int* __restrict__ idxp) {
    int j = blockIdx.x * 256 + threadIdx.x;
    int idx = *idxp;
    int Kc = (idx == 0) ? 512 : 1024;
    if (j >= KMAX) return;
    if (j < Kc) {
        const float* cbh = (idx == 1) ? cb1 : cb2;
        const float* cp = (j < 512) ? (cb0 + (size_t)j * 256) : (cbh + (size_t)(j - 512) * 256);
        float s = 0.f;
        for (int d = 0; d < 256; d++) { float v = cp[d]; s += v * v; }
        g_cn2[j] = s;
    } else g_cn2[j] = 0.f;
}

// ---------------- VQ: R1 semantics, j-pairs packed into fma.rn.f32x2 ----------
// per-score accumulation chain order identical to R1/R6 -> identical argmins
__global__ void vq_kernel(const float* __restrict__ cb0, const float* __restrict__ cb1,
                          const float* __restrict__ cb2, const int* __restrict__ idxp) {
    __shared__ float fS[32 * 65];
    __shared__ __align__(16) float cS[32 * 66];   // stride 66 -> 8B-aligned j-pairs
    __shared__ float cns[64];
    __shared__ float redS[64 * 16];
    __shared__ int   redI[64 * 16];

    int n = blockIdx.x, tid = threadIdx.x;
    int tx = tid & 15, ty = tid >> 4;
    int idx = *idxp;
    int Kc = (idx == 0) ? 512 : 1024;
    const float* cbh = (idx == 1) ? cb1 : cb2;
    const float* feaN = g_fea + (size_t)n * CH;

    float bestS[4] = {-1e30f, -1e30f, -1e30f, -1e30f};
    int   bestI[4] = {0, 0, 0, 0};

    int T = Kc >> 6;
    for (int ct = 0; ct < T; ct++) {
        __syncthreads();
        int cbase = ct * 64;
        const float* cp = (cbase < 512) ? (cb0 + (size_t)cbase * 256)
                                        : (cbh + (size_t)(cbase - 512) * 256);
        if (tid < 64) cns[tid] = g_cn2[cbase + tid];

        unsigned long long acc2[4][2];
#pragma unroll
        for (int i = 0; i < 4; i++) { acc2[i][0] = 0ull; acc2[i][1] = 0ull; }

        for (int kc = 0; kc < 8; kc++) {
            __syncthreads();
#pragma unroll
            for (int r = 0; r < 8; r++) {
                int L = tid + 256 * r;
                int d = L >> 6, s = L & 63;
                fS[d * 65 + s] = feaN[(size_t)(kc * 32 + d) * 64 + s];
                int j = L >> 5, dd = L & 31;
                cS[dd * 66 + j] = cp[(size_t)j * 256 + kc * 32 + dd];
            }
            __syncthreads();
#pragma unroll
            for (int d = 0; d < 32; d++) {
                // d*66 + ty*4 is even -> 8B aligned
                unsigned long long c01 = *(const unsigned long long*)&cS[d * 66 + ty * 4];
                unsigned long long c23 = *(const unsigned long long*)&cS[d * 66 + ty * 4 + 2];
#pragma unroll
                for (int i = 0; i < 4; i++) {
                    float a = fS[d * 65 + tx + 16 * i];
                    unsigned long long a2 = pk2(a, a);
                    FMA2(acc2[i][0], a2, c01);
                    FMA2(acc2[i][1], a2, c23);
                }
            }
        }
#pragma unroll
        for (int i = 0; i < 4; i++) {
            float2 p01 = upk2(acc2[i][0]);
            float2 p23 = upk2(acc2[i][1]);
            float vj[4] = {p01.x, p01.y, p23.x, p23.y};
#pragma unroll
            for (int j = 0; j < 4; j++) {
                float sc = vj[j] - 0.5f * cns[ty * 4 + j];
                if (sc > bestS[i]) { bestS[i] = sc; bestI[i] = cbase + ty * 4 + j; }
            }
        }
    }

    __syncthreads();
#pragma unroll
    for (int i = 0; i < 4; i++) {
        redS[(tx + 16 * i) * 16 + ty] = bestS[i];
        redI[(tx + 16 * i) * 16 + ty] = bestI[i];
    }
    __syncthreads();
    if (tid < 64) {
        float bs = redS[tid * 16]; int bi = redI[tid * 16];
        for (int t = 1; t < 16; t++) {
            float s = redS[tid * 16 + t]; int ii = redI[tid * 16 + t];
            if (s > bs || (s == bs && ii < bi)) { bs = s; bi = ii; }
        }
        g_bi[n * 64 + tid] = bi;
    }
}

// ---------------- gather: R6 verbatim ----------------
__global__ void gather_kernel(const float* __restrict__ cb0, const float* __restrict__ cb1,
                              const float* __restrict__ cb2, const int* __restrict__ idxp) {
    __shared__ int sbi[64];
    __shared__ float wsum[8];
    int n = blockIdx.x, tid = threadIdx.x;
    int idx = *idxp;
    const float* cbh = (idx == 1) ? cb1 : cb2;
    if (tid < 64) {
        int b = g_bi[n * 64 + tid];
        sbi[tid] = b;
        atomicAdd(&g_counts[b], 1);
    }
    __syncthreads();
    const float* feaN = g_fea + (size_t)n * CH;
    float local = 0.f;
    for (int e = tid; e < CH; e += 256) {
        int d = e >> 6, s = e & 63;
        int b = sbi[s];
        float q = (b < 512) ? cb0[(size_t)b * 256 + d] : cbh[(size_t)(b - 512) * 256 + d];
        float f = feaN[e];
        float df = q - f;
        local += df * df;
        __nv_bfloat16 qh, ql;
        split2(q, qh, ql);
        size_t rr = ((size_t)n * 64 + s) * 256 + d;
        g_qh[rr] = qh;
        g_ql[rr] = ql;
    }
#pragma unroll
    for (int o = 16; o; o >>= 1) local += __shfl_xor_sync(0xffffffffu, local, o);
    if ((tid & 31) == 0) wsum[tid >> 5] = local;
    __syncthreads();
    if (tid == 0) {
        float t = 0.f;
        for (int w = 0; w < 8; w++) t += wsum[w];
        atomicAdd(&g_lossSum, t);
    }
}

// ---------------- prep: fc1 weight permute + split (R6 verbatim) --------------
__global__ void prep_f1w_kernel(const float* __restrict__ f1w) {
    int gid = blockIdx.x * 256 + threadIdx.x;   // 512*16384
    int h = gid >> 14, kp = gid & 16383;
    int s = kp >> 8, oc = kp & 255;
    float v = f1w[(size_t)h * CH + oc * 64 + s];
    split2(v, g_f1wh[gid], g_f1wl[gid]);
}

// ---------------- fc1 TC GEMM (bf16x3, R6 verbatim) ----------------
__global__ void __launch_bounds__(256) fc1_tc_kernel(const float* __restrict__ f1b) {
    constexpr int BM = 128, BN = 64, LDK = 40, K = CH;
    constexpr int BOFF = 2 * 2 * BM * LDK;

    const __nv_bfloat16* Ag[2] = {g_qh, g_ql};
    const __nv_bfloat16* Bg[2] = {g_f1wh, g_f1wl};

    extern __shared__ __nv_bfloat16 sm[];

    const int tid = threadIdx.x;
    const int warp = tid >> 5, lane = tid & 31;
    const int wm = warp & 1, wn = warp >> 1;
    const size_t m0 = (size_t)blockIdx.y * BM;
    const int n0 = blockIdx.x * BN;

    float acc[4][2][4];
#pragma unroll
    for (int i = 0; i < 4; i++)
#pragma unroll
        for (int j = 0; j < 2; j++)
#pragma unroll
            for (int q = 0; q < 4; q++) acc[i][j][q] = 0.f;

    auto issue = [&](int kt) {
        int st = kt & 1;
        size_t kb = (size_t)kt * 32;
#pragma unroll
        for (int p = 0; p < 2; p++) {
            for (int i = tid; i < BM * 4; i += 256) {
                int r = i >> 2, c = (i & 3) * 8;
                cpasync16(s2u(&sm[((p * 2 + st) * BM + r) * LDK + c]),
                          Ag[p] + (m0 + r) * K + kb + c);
            }
            for (int i = tid; i < BN * 4; i += 256) {
                int r = i >> 2, c = (i & 3) * 8;
                cpasync16(s2u(&sm[BOFF + ((p * 2 + st) * BN + r) * LDK + c]),
                          Bg[p] + (size_t)(n0 + r) * K + kb + c);
            }
        }
        asm volatile("cp.async.commit_group;");
    };

    constexpr int NK = K / 32;
    issue(0);
    for (int kt = 0; kt < NK; kt++) {
        if (kt + 1 < NK) {
            issue(kt + 1);
            asm volatile("cp.async.wait_group 1;");
        } else {
            asm volatile("cp.async.wait_group 0;");
        }
        __syncthreads();
        int st = kt & 1;
#pragma unroll
        for (int ks = 0; ks < 2; ks++) {
            int arow = wm * 64 + (lane & 15);
            int acol = ks * 16 + (lane >> 4) * 8;
            int brow = wn * 16 + (lane & 7) + ((lane >> 4) << 3);
            int bcol = ks * 16 + ((lane >> 3) & 1) * 8;

            uint32_t a0[4][4], a1[4][4], b0[4], b1[4];
#pragma unroll
            for (int mi = 0; mi < 4; mi++) {
                ldsm4(a0[mi], s2u(&sm[((0 * 2 + st) * BM + arow + mi * 16) * LDK + acol]));
                ldsm4(a1[mi], s2u(&sm[((1 * 2 + st) * BM + arow + mi * 16) * LDK + acol]));
            }
            ldsm4(b0, s2u(&sm[BOFF + ((0 * 2 + st) * BN + brow) * LDK + bcol]));
            ldsm4(b1, s2u(&sm[BOFF + ((1 * 2 + st) * BN + brow) * LDK + bcol]));

#pragma unroll
            for (int mi = 0; mi < 4; mi++)
#pragma unroll
                for (int j = 0; j < 2; j++) {
                    mma16816(acc[mi][j], a0[mi], &b0[j * 2]);
                    mma16816(acc[mi][j], a0[mi], &b1[j * 2]);
                    mma16816(acc[mi][j], a1[mi], &b0[j * 2]);
                }
        }
        __syncthreads();
    }

#pragma unroll
    for (int mi = 0; mi < 4; mi++)
#pragma unroll
        for (int j = 0; j < 2; j++) {
            size_t row = m0 + wm * 64 + mi * 16 + (lane >> 2);
            int col = n0 + wn * 16 + j * 8 + (lane & 3) * 2;
            float* c = acc[mi][j];
#pragma unroll
            for (int half = 0; half < 2; half++) {
                size_t r = row + half * 8;
                float a0v = c[half * 2 + 0] + __ldg(&f1b[col]);
                float a1v = c[half * 2 + 1] + __ldg(&f1b[col + 1]);
                float2 o;
                o.x = 0.5f * a0v * (1.f + erff(a0v * 0.70710678118654752f));
                o.y = 0.5f * a1v * (1.f + erff(a1v * 0.70710678118654752f));
                *reinterpret_cast<float2*>(&g_h1[r * HID + col]) = o;
            }
        }
}

// ---------------- fc2 (R1 verbatim) ----------------
__global__ void fc2_kernel(const float* __restrict__ w, const float* __restrict__ b,
                           float* __restrict__ out) {
    int gwarp = (blockIdx.x * 256 + threadIdx.x) >> 5;
    int lane = threadIdx.x & 31;
    if (gwarp >= NB) return;
    float acc[10];
#pragma unroll
    for (int o = 0; o < 10; o++) acc[o] = 0.f;
    const float* hrow = g_h1 + (size_t)gwarp * HID;
    for (int k = lane; k < HID; k += 32) {
        float h = hrow[k];
#pragma unroll
        for (int o = 0; o < 10; o++) acc[o] += h * w[o * HID + k];
    }
#pragma unroll
    for (int o = 0; o < 10; o++)
#pragma unroll
        for (int off = 16; off; off >>= 1) acc[o] += __shfl_xor_sync(0xffffffffu, acc[o], off);
    if (lane == 0) {
#pragma unroll
        for (int o = 0; o < 10; o++) out[(size_t)gwarp * 10 + o] = acc[o] + b[o];
    }
}

// ---------------- finalize (R1 verbatim) ----------------
__global__ void finalize_kernel(float* __restrict__ out) {
    __shared__ float wsum[8];
    int tid = threadIdx.x;
    float local = 0.f;
    for (int k = tid; k < KMAX; k += 256) {
        float p = (float)g_counts[k] * (1.0f / 131072.0f);
        local += p * logf(p + 1e-10f);
    }
#pragma unroll
    for (int o = 16; o; o >>= 1) local += __shfl_xor_sync(0xffffffffu, local, o);
    if ((tid & 31) == 0) wsum[tid >> 5] = local;
    __syncthreads();
    if (tid == 0) {
        float t = 0.f;
        for (int w = 0; w < 8; w++) t += wsum[w];
        out[20480] = 1.25f * g_lossSum * (1.0f / 33554432.0f);
        out[20481] = expf(-t);
    }
}

// ---------------- launch ----------------
extern "C" void kernel_launch(void* const* d_in, const int* in_sizes, int n_in,
                              void* d_out, int out_size) {
    const float* x    = (const float*)d_in[0];
    const int*   idxp = (const int*)  d_in[1];
    const float* w1   = (const float*)d_in[2];
    const float* b1   = (const float*)d_in[3];
    const float* w2   = (const float*)d_in[4];
    const float* b2   = (const float*)d_in[5];
    const float* cb0  = (const float*)d_in[6];
    const float* cb1  = (const float*)d_in[7];
    const float* cb2  = (const float*)d_in[8];
    const float* f1w  = (const float*)d_in[9];
    const float* f1b  = (const float*)d_in[10];
    const float* f2w  = (const float*)d_in[11];
    const float* f2b  = (const float*)d_in[12];
    float* out = (float*)d_out;

    constexpr int SMF = (2 * 2 * 128 + 2 * 2 * 64) * 40 * 2;  // 61440 B
    cudaFuncSetAttribute(fc1_tc_kernel, cudaFuncAttributeMaxDynamicSharedMemorySize, SMF);

    zero_stats_kernel<<<1, 1024>>>();
    prep_f1w_kernel<<<32768, 256>>>(f1w);
    conv1_kernel<<<NB, 256>>>(x, w1, b1);
    conv2_kernel<<<dim3(4, NB), 256>>>(w2, b2);
    cn2_kernel<<<4, 256>>>(cb0, cb1, cb2, idxp);
    vq_kernel<<<NB, 256>>>(cb0, cb1, cb2, idxp);
    gather_kernel<<<NB, 256>>>(cb0, cb1, cb2, idxp);
    fc1_tc_kernel<<<dim3(8, 16), 256, SMF>>>(f1b);
    fc2_kernel<<<NB / 8, 256>>>(f2w, f2b, out);
    finalize_kernel<<<1, 256>>>(out);
}

// round 8
// speedup vs baseline: 2.1091x; 2.0391x over previous
#include <cuda_runtime.h>
#include <cuda_bf16.h>
#include <math.h>
#include <stdint.h>

// ---------------- problem constants ----------------
#define NB    2048
#define NPIX1 256
#define C1    128
#define C2    256
#define SPIX  64
#define NROWS (NB*SPIX)
#define DDIM  256
#define KMAX  1024
#define CH    16384
#define HID   512
#define K2    2048

// ---------------- scratch ----------------
__device__ float         g_relu1[(size_t)NB * C1 * NPIX1];
__device__ float         g_xcol [(size_t)NROWS * K2 / 64 * 64];  // [n][k'][64spix] = 1GB
__device__ float         g_w2p  [K2 * 256];                      // [k'][oc]
__device__ float         g_fea  [(size_t)NB * CH];               // [n][oc][spix]
__device__ float         g_feaT [(size_t)NROWS * DDIM];          // [row][oc] fp32
__device__ __nv_bfloat16 g_feah[(size_t)NROWS * DDIM], g_feal[(size_t)NROWS * DDIM];
__device__ __nv_bfloat16 g_cbh[KMAX * DDIM], g_cbl[KMAX * DDIM];
__device__ float         g_cbF[KMAX * DDIM];
__device__ float         g_cn2[KMAX];
__device__ float         g_scores[(size_t)NROWS * KMAX];
__device__ int           g_bi[NROWS];
__device__ __nv_bfloat16 g_qh[(size_t)NB * CH], g_ql[(size_t)NB * CH];
__device__ __nv_bfloat16 g_f1wh[(size_t)HID * CH], g_f1wl[(size_t)HID * CH];
__device__ float         g_h1[(size_t)NB * HID];
__device__ int           g_counts[KMAX];
__device__ float         g_lossSum;
__device__ int           g_Kc;

// ---------------- helpers ----------------
__device__ __forceinline__ uint32_t s2u(const void* p) {
    return (uint32_t)__cvta_generic_to_shared(p);
}
__device__ __forceinline__ void cpasync16(uint32_t s, const void* g) {
    asm volatile("cp.async.cg.shared.global [%0], [%1], 16;" :: "r"(s), "l"(g));
}
__device__ __forceinline__ void ldsm4(uint32_t* r, uint32_t s) {
    asm volatile("ldmatrix.sync.aligned.m8n8.x4.shared.b16 {%0,%1,%2,%3}, [%4];"
                 : "=r"(r[0]), "=r"(r[1]), "=r"(r[2]), "=r"(r[3]) : "r"(s));
}
__device__ __forceinline__ void mma16816(float* c, const uint32_t* a, const uint32_t* b) {
    asm volatile("mma.sync.aligned.m16n8k16.row.col.f32.bf16.bf16.f32 "
                 "{%0,%1,%2,%3}, {%4,%5,%6,%7}, {%8,%9}, {%0,%1,%2,%3};"
                 : "+f"(c[0]), "+f"(c[1]), "+f"(c[2]), "+f"(c[3])
                 : "r"(a[0]), "r"(a[1]), "r"(a[2]), "r"(a[3]), "r"(b[0]), "r"(b[1]));
}
__device__ __forceinline__ void split2(float v, __nv_bfloat16& h, __nv_bfloat16& l) {
    h = __float2bfloat16(v);
    l = __float2bfloat16(v - __bfloat162float(h));
}
__device__ __forceinline__ unsigned long long pk2(float x, float y) {
    unsigned long long r;
    asm("mov.b64 %0, {%1, %2};" : "=l"(r) : "f"(x), "f"(y));
    return r;
}
__device__ __forceinline__ float2 upk2(unsigned long long v) {
    float2 f;
    asm("mov.b64 {%0, %1}, %2;" : "=f"(f.x), "=f"(f.y) : "l"(v));
    return f;
}
#define FMA2(d, a, b) asm("fma.rn.f32x2 %0, %1, %2, %0;" : "+l"(d) : "l"(a), "l"(b))

// ---------------- zero stats ----------------
__global__ void zero_stats_kernel() {
    int t = threadIdx.x;
    if (t < KMAX) g_counts[t] = 0;
    if (t == 0)   g_lossSum = 0.f;
}

// ---------------- conv1 (R1 verbatim) ----------------
__global__ void conv1_kernel(const float* __restrict__ x,
                             const float* __restrict__ w1,
                             const float* __restrict__ b1) {
    __shared__ float sIn[3 * 32 * 32];
    __shared__ float sW [128 * 48];
    __shared__ float sB [128];
    int n = blockIdx.x, tid = threadIdx.x;
    for (int i = tid; i < 3072; i += 256) sIn[i] = x[(size_t)n * 3072 + i];
    for (int i = tid; i < 6144; i += 256) sW[i]  = w1[i];
    if (tid < 128) sB[tid] = b1[tid];
    __syncthreads();
    int oh = tid >> 4, ow = tid & 15;
    float a[48];
#pragma unroll
    for (int ci = 0; ci < 3; ci++)
#pragma unroll
        for (int kh = 0; kh < 4; kh++)
#pragma unroll
            for (int kw = 0; kw < 4; kw++) {
                int ih = 2 * oh - 1 + kh, iw = 2 * ow - 1 + kw;
                bool v = (ih >= 0 && ih < 32 && iw >= 0 && iw < 32);
                a[ci * 16 + kh * 4 + kw] = v ? sIn[ci * 1024 + ih * 32 + iw] : 0.f;
            }
    float* outp = g_relu1 + (size_t)n * (C1 * NPIX1) + tid;
    for (int oc = 0; oc < 128; oc++) {
        float acc = sB[oc];
#pragma unroll
        for (int t = 0; t < 48; t++) acc += a[t] * sW[oc * 48 + t];
        outp[(size_t)oc * 256] = fmaxf(acc, 0.f);
    }
}

// ---------------- im2col fp32: g_xcol[n][k'][spix], k' = kcblk*128+tap*8+ciL ---
__global__ void im2col_kernel() {
    int kcblk = blockIdx.x;   // 0..15
    int n     = blockIdx.y;   // 0..2047
    int tid = threadIdx.x;
    for (int t = tid; t < 8192; t += 256) {
        int kl = t >> 6, s = t & 63;
        int tap = kl >> 3, ciL = kl & 7;
        int ci = kcblk * 8 + ciL;
        int kh = tap >> 2, kw = tap & 3;
        int oh = s >> 3, ow = s & 7;
        int ih = 2 * oh - 1 + kh, iw = 2 * ow - 1 + kw;
        float v = 0.f;
        if (ih >= 0 && ih < 16 && iw >= 0 && iw < 16)
            v = g_relu1[((size_t)n * 128 + ci) * 256 + ih * 16 + iw];
        g_xcol[(((size_t)n * 16 + kcblk) * 128 + kl) * 64 + s] = v;
    }
}

// ---------------- prep: permuted w2p[k'][oc] ----------------
__global__ void prep_w2p_kernel(const float* __restrict__ w2) {
    int gid = blockIdx.x * 256 + threadIdx.x;   // 2048*256
    int oc = gid & 255, kp = gid >> 8;
    int kcblk = kp >> 7, r = kp & 127;
    int tap = r >> 3, ciL = r & 7;
    int gk = (kcblk * 8 + ciL) * 16 + tap;
    g_w2p[gid] = w2[(size_t)oc * 2048 + gk];
}

// ---------------- conv2 GEMM: fea[n][oc][spix], R1-order FFMA2 chains ---------
__global__ void __launch_bounds__(256, 2) conv2_gemm_kernel(const float* __restrict__ b2) {
    extern __shared__ __align__(16) float cs[];
    float* inS = cs;                  // [2][32][68]
    float* wS  = cs + 2 * 32 * 68;    // [2][32][264]
    int n = blockIdx.x, tid = threadIdx.x;
    int tx = tid & 15, ty = tid >> 4;
    const float* xrow = g_xcol + (size_t)n * K2 * 64;

    unsigned long long acc2[4][8];
#pragma unroll
    for (int i = 0; i < 4; i++)
#pragma unroll
        for (int p = 0; p < 8; p++) acc2[i][p] = 0ull;

    auto issue = [&](int kt) {
        int st = kt & 1, k0 = kt * 32;
        for (int i = tid; i < 512; i += 256) {
            int r = i >> 4, seg = i & 15;
            cpasync16(s2u(&inS[(st * 32 + r) * 68 + seg * 4]),
                      xrow + (size_t)(k0 + r) * 64 + seg * 4);
        }
        for (int i = tid; i < 2048; i += 256) {
            int r = i >> 6, seg = i & 63;
            cpasync16(s2u(&wS[(st * 32 + r) * 264 + seg * 4]),
                      g_w2p + (size_t)(k0 + r) * 256 + seg * 4);
        }
        asm volatile("cp.async.commit_group;");
    };

    issue(0);
    for (int kt = 0; kt < 64; kt++) {
        if (kt + 1 < 64) {
            issue(kt + 1);
            asm volatile("cp.async.wait_group 1;");
        } else {
            asm volatile("cp.async.wait_group 0;");
        }
        __syncthreads();
        int st = kt & 1;
#pragma unroll
        for (int k = 0; k < 32; k++) {
            float4 a4 = *(const float4*)&inS[(st * 32 + k) * 68 + tx * 4];
            const ulonglong2* wp = (const ulonglong2*)&wS[(st * 32 + k) * 264 + ty * 16];
            ulonglong2 w0 = wp[0], w1 = wp[1], w2v = wp[2], w3 = wp[3];
            unsigned long long aw[4] = {pk2(a4.x, a4.x), pk2(a4.y, a4.y),
                                        pk2(a4.z, a4.z), pk2(a4.w, a4.w)};
#pragma unroll
            for (int i = 0; i < 4; i++) {
                FMA2(acc2[i][0], aw[i], w0.x);  FMA2(acc2[i][1], aw[i], w0.y);
                FMA2(acc2[i][2], aw[i], w1.x);  FMA2(acc2[i][3], aw[i], w1.y);
                FMA2(acc2[i][4], aw[i], w2v.x); FMA2(acc2[i][5], aw[i], w2v.y);
                FMA2(acc2[i][6], aw[i], w3.x);  FMA2(acc2[i][7], aw[i], w3.y);
            }
        }
        __syncthreads();
    }

    float* feaN = g_fea + (size_t)n * CH;
#pragma unroll
    for (int p = 0; p < 8; p++) {
        float2 v0 = upk2(acc2[0][p]), v1 = upk2(acc2[1][p]);
        float2 v2 = upk2(acc2[2][p]), v3 = upk2(acc2[3][p]);
        int oc0 = ty * 16 + p * 2, oc1 = oc0 + 1;
        float b0 = b2[oc0], b1 = b2[oc1];
        float4 o0 = {fmaxf(v0.x + b0, 0.f), fmaxf(v1.x + b0, 0.f),
                     fmaxf(v2.x + b0, 0.f), fmaxf(v3.x + b0, 0.f)};
        float4 o1 = {fmaxf(v0.y + b1, 0.f), fmaxf(v1.y + b1, 0.f),
                     fmaxf(v2.y + b1, 0.f), fmaxf(v3.y + b1, 0.f)};
        *(float4*)&feaN[(size_t)oc0 * 64 + tx * 4] = o0;
        *(float4*)&feaN[(size_t)oc1 * 64 + tx * 4] = o1;
    }
}

// ---------------- prep: codes fp32 + split + norms + Kc (R3 verbatim) ---------
__global__ void prep_codes_kernel(const float* __restrict__ cb0, const float* __restrict__ cb1,
                                  const float* __restrict__ cb2, const int* __restrict__ idxp) {
    __shared__ float wsum[8];
    int j = blockIdx.x, d = threadIdx.x;
    int idx = *idxp;
    int Kc = (idx == 0) ? 512 : 1024;
    if (j == 0 && d == 0) g_Kc = Kc;
    float v = 0.f;
    if (j < Kc) {
        const float* cbh = (idx == 1) ? cb1 : cb2;
        v = (j < 512) ? cb0[j * 256 + d] : cbh[(j - 512) * 256 + d];
    }
    g_cbF[j * 256 + d] = v;
    split2(v, g_cbh[j * 256 + d], g_cbl[j * 256 + d]);
    float sq = v * v;
#pragma unroll
    for (int o = 16; o; o >>= 1) sq += __shfl_xor_sync(0xffffffffu, sq, o);
    if ((d & 31) == 0) wsum[d >> 5] = sq;
    __syncthreads();
    if (d == 0) {
        float t = 0.f;
        for (int w = 0; w < 8; w++) t += wsum[w];
        g_cn2[j] = t;
    }
}

// ---------------- fea transpose: feaT fp32 + feah/feal bf16 (row-major) -------
__global__ void feasplit_kernel() {
    extern __shared__ float sf[];   // [256][65]
    int n = blockIdx.x, tid = threadIdx.x;
    const float* feaN = g_fea + (size_t)n * CH;
    for (int t = tid; t < 16384; t += 256) {
        int oc = t >> 6, s = t & 63;
        sf[oc * 65 + s] = feaN[t];
    }
    __syncthreads();
    for (int t = tid; t < 16384; t += 256) {
        int srow = t >> 8, oc = t & 255;
        float v = sf[oc * 65 + srow];
        size_t r = ((size_t)n * 64 + srow) * 256 + oc;
        g_feaT[r] = v;
        split2(v, g_feah[r], g_feal[r]);
    }
}

// ---------------- VQ scores GEMM bf16x3 (R3 EPI=1 concrete) -------------------
__global__ void __launch_bounds__(256) scores_kernel() {
    constexpr int BM = 128, BN = 128, LDK = 40, K = DDIM;
    constexpr int BOFF = 2 * 2 * BM * LDK;
    if ((int)blockIdx.x * BN >= g_Kc) return;

    const __nv_bfloat16* Ag[2] = {g_feah, g_feal};
    const __nv_bfloat16* Bg[2] = {g_cbh, g_cbl};

    extern __shared__ __nv_bfloat16 sm[];
    const int tid = threadIdx.x;
    const int warp = tid >> 5, lane = tid & 31;
    const int wm = warp & 1, wn = warp >> 1;
    const size_t m0 = (size_t)blockIdx.y * BM;
    const int n0 = blockIdx.x * BN;

    float acc[4][4][4];
#pragma unroll
    for (int i = 0; i < 4; i++)
#pragma unroll
        for (int j = 0; j < 4; j++)
#pragma unroll
            for (int q = 0; q < 4; q++) acc[i][j][q] = 0.f;

    auto issue = [&](int kt) {
        int st = kt & 1;
        size_t kb = (size_t)kt * 32;
#pragma unroll
        for (int p = 0; p < 2; p++) {
            for (int i = tid; i < BM * 4; i += 256) {
                int r = i >> 2, c = (i & 3) * 8;
                cpasync16(s2u(&sm[((p * 2 + st) * BM + r) * LDK + c]),
                          Ag[p] + (m0 + r) * K + kb + c);
            }
            for (int i = tid; i < BN * 4; i += 256) {
                int r = i >> 2, c = (i & 3) * 8;
                cpasync16(s2u(&sm[BOFF + ((p * 2 + st) * BN + r) * LDK + c]),
                          Bg[p] + (size_t)(n0 + r) * K + kb + c);
            }
        }
        asm volatile("cp.async.commit_group;");
    };

    constexpr int NK = K / 32;  // 8
    issue(0);
    for (int kt = 0; kt < NK; kt++) {
        if (kt + 1 < NK) {
            issue(kt + 1);
            asm volatile("cp.async.wait_group 1;");
        } else {
            asm volatile("cp.async.wait_group 0;");
        }
        __syncthreads();
        int st = kt & 1;
#pragma unroll
        for (int ks = 0; ks < 2; ks++) {
            int arow = wm * 64 + (lane & 15);
            int acol = ks * 16 + (lane >> 4) * 8;
            int brow = wn * 32 + (lane & 7) + ((lane >> 4) << 3);
            int bcol = ks * 16 + ((lane >> 3) & 1) * 8;

            uint32_t a0[4][4], a1[4][4], b0[2][4], b1[2][4];
#pragma unroll
            for (int mi = 0; mi < 4; mi++) {
                ldsm4(a0[mi], s2u(&sm[((0 * 2 + st) * BM + arow + mi * 16) * LDK + acol]));
                ldsm4(a1[mi], s2u(&sm[((1 * 2 + st) * BM + arow + mi * 16) * LDK + acol]));
            }
#pragma unroll
            for (int g = 0; g < 2; g++) {
                ldsm4(b0[g], s2u(&sm[BOFF + ((0 * 2 + st) * BN + brow + g * 16) * LDK + bcol]));
                ldsm4(b1[g], s2u(&sm[BOFF + ((1 * 2 + st) * BN + brow + g * 16) * LDK + bcol]));
            }
#pragma unroll
            for (int mi = 0; mi < 4; mi++)
#pragma unroll
                for (int j = 0; j < 4; j++) {
                    int g = j >> 1, o = (j & 1) * 2;
                    mma16816(acc[mi][j], a0[mi], &b0[g][o]);
                    mma16816(acc[mi][j], a0[mi], &b1[g][o]);
                    mma16816(acc[mi][j], a1[mi], &b0[g][o]);
                }
        }
        __syncthreads();
    }

#pragma unroll
    for (int mi = 0; mi < 4; mi++)
#pragma unroll
        for (int j = 0; j < 4; j++) {
            size_t row = m0 + wm * 64 + mi * 16 + (lane >> 2);
            int col = n0 + wn * 32 + j * 8 + (lane & 3) * 2;
            float* c = acc[mi][j];
#pragma unroll
            for (int half = 0; half < 2; half++) {
                size_t r = row + half * 8;
                float2 o;
                o.x = c[half * 2 + 0] - 0.5f * __ldg(&g_cn2[col]);
                o.y = c[half * 2 + 1] - 0.5f * __ldg(&g_cn2[col + 1]);
                *reinterpret_cast<float2*>(&g_scores[r * KMAX + col]) = o;
            }
        }
}

// ---------------- argmax top-2 + exact fp32 refine (R3, feaT row-major) -------
__global__ void argmax_refine_kernel() {
    int row = (blockIdx.x * 256 + threadIdx.x) >> 5;
    int lane = threadIdx.x & 31;
    int Kc = g_Kc;
    const float* sc = g_scores + (size_t)row * KMAX;

    float s1 = -3.4e38f, s2c = -3.4e38f;
    int i1 = -1, i2 = -1;
    auto upd = [&](float v, int c) {
        if (c == i1 || c == i2 || c < 0) return;
        if (v > s1 || (v == s1 && c < i1)) { s2c = s1; i2 = i1; s1 = v; i1 = c; }
        else if (v > s2c || (v == s2c && c < i2)) { s2c = v; i2 = c; }
    };
    for (int c = lane; c < Kc; c += 32) upd(sc[c], c);
#pragma unroll
    for (int off = 16; off; off >>= 1) {
        float os1 = __shfl_xor_sync(0xffffffffu, s1, off);
        int   oi1 = __shfl_xor_sync(0xffffffffu, i1, off);
        float os2 = __shfl_xor_sync(0xffffffffu, s2c, off);
        int   oi2 = __shfl_xor_sync(0xffffffffu, i2, off);
        upd(os1, oi1);
        upd(os2, oi2);
    }

    const float* f  = g_feaT + (size_t)row * DDIM;
    const float* c0 = g_cbF + (size_t)i1 * DDIM;
    const float* c1 = g_cbF + (size_t)i2 * DDIM;
    float d0 = 0.f, d1 = 0.f;
    for (int k = lane; k < DDIM; k += 32) {
        float fv = f[k];
        d0 += fv * c0[k];
        d1 += fv * c1[k];
    }
#pragma unroll
    for (int off = 16; off; off >>= 1) {
        d0 += __shfl_xor_sync(0xffffffffu, d0, off);
        d1 += __shfl_xor_sync(0xffffffffu, d1, off);
    }
    float e0 = d0 - 0.5f * g_cn2[i1];
    float e1 = d1 - 0.5f * g_cn2[i2];
    int best = (e1 > e0 || (e1 == e0 && i2 < i1)) ? i2 : i1;
    if (lane == 0) g_bi[row] = best;
}

// ---------------- gather: coalesced via feaT -----------------------------------
__global__ void gather_kernel(const float* __restrict__ cb0, const float* __restrict__ cb1,
                              const float* __restrict__ cb2, const int* __restrict__ idxp) {
    __shared__ int sbi[64];
    __shared__ float wsum[8];
    int n = blockIdx.x, tid = threadIdx.x;
    int idx = *idxp;
    const float* cbh = (idx == 1) ? cb1 : cb2;
    if (tid < 64) {
        int b = g_bi[n * 64 + tid];
        sbi[tid] = b;
        atomicAdd(&g_counts[b], 1);
    }
    __syncthreads();
    float local = 0.f;
    for (int t = tid; t < 16384; t += 256) {
        int srow = t >> 8, oc = t & 255;
        int b = sbi[srow];
        float q = (b < 512) ? cb0[(size_t)b * 256 + oc] : cbh[(size_t)(b - 512) * 256 + oc];
        size_t r = ((size_t)n * 64 + srow) * 256 + oc;
        float fv = g_feaT[r];
        float df = q - fv;
        local += df * df;
        split2(q, g_qh[r], g_ql[r]);
    }
#pragma unroll
    for (int o = 16; o; o >>= 1) local += __shfl_xor_sync(0xffffffffu, local, o);
    if ((tid & 31) == 0) wsum[tid >> 5] = local;
    __syncthreads();
    if (tid == 0) {
        float t = 0.f;
        for (int w = 0; w < 8; w++) t += wsum[w];
        atomicAdd(&g_lossSum, t);
    }
}

// ---------------- prep: fc1 weight permute + split (R6 verbatim) --------------
__global__ void prep_f1w_kernel(const float* __restrict__ f1w) {
    int gid = blockIdx.x * 256 + threadIdx.x;
    int h = gid >> 14, kp = gid & 16383;
    int s = kp >> 8, oc = kp & 255;
    float v = f1w[(size_t)h * CH + oc * 64 + s];
    split2(v, g_f1wh[gid], g_f1wl[gid]);
}

// ---------------- fc1 TC GEMM (R6 verbatim) ----------------
__global__ void __launch_bounds__(256) fc1_tc_kernel(const float* __restrict__ f1b) {
    constexpr int BM = 128, BN = 64, LDK = 40, K = CH;
    constexpr int BOFF = 2 * 2 * BM * LDK;
    const __nv_bfloat16* Ag[2] = {g_qh, g_ql};
    const __nv_bfloat16* Bg[2] = {g_f1wh, g_f1wl};
    extern __shared__ __nv_bfloat16 sm[];
    const int tid = threadIdx.x;
    const int warp = tid >> 5, lane = tid & 31;
    const int wm = warp & 1, wn = warp >> 1;
    const size_t m0 = (size_t)blockIdx.y * BM;
    const int n0 = blockIdx.x * BN;

    float acc[4][2][4];
#pragma unroll
    for (int i = 0; i < 4; i++)
#pragma unroll
        for (int j = 0; j < 2; j++)
#pragma unroll
            for (int q = 0; q < 4; q++) acc[i][j][q] = 0.f;

    auto issue = [&](int kt) {
        int st = kt & 1;
        size_t kb = (size_t)kt * 32;
#pragma unroll
        for (int p = 0; p < 2; p++) {
            for (int i = tid; i < BM * 4; i += 256) {
                int r = i >> 2, c = (i & 3) * 8;
                cpasync16(s2u(&sm[((p * 2 + st) * BM + r) * LDK + c]),
                          Ag[p] + (m0 + r) * K + kb + c);
            }
            for (int i = tid; i < BN * 4; i += 256) {
                int r = i >> 2, c = (i & 3) * 8;
                cpasync16(s2u(&sm[BOFF + ((p * 2 + st) * BN + r) * LDK + c]),
                          Bg[p] + (size_t)(n0 + r) * K + kb + c);
            }
        }
        asm volatile("cp.async.commit_group;");
    };

    constexpr int NK = K / 32;
    issue(0);
    for (int kt = 0; kt < NK; kt++) {
        if (kt + 1 < NK) {
            issue(kt + 1);
            asm volatile("cp.async.wait_group 1;");
        } else {
            asm volatile("cp.async.wait_group 0;");
        }
        __syncthreads();
        int st = kt & 1;
#pragma unroll
        for (int ks = 0; ks < 2; ks++) {
            int arow = wm * 64 + (lane & 15);
            int acol = ks * 16 + (lane >> 4) * 8;
            int brow = wn * 16 + (lane & 7) + ((lane >> 4) << 3);
            int bcol = ks * 16 + ((lane >> 3) & 1) * 8;
            uint32_t a0[4][4], a1[4][4], b0[4], b1[4];
#pragma unroll
            for (int mi = 0; mi < 4; mi++) {
                ldsm4(a0[mi], s2u(&sm[((0 * 2 + st) * BM + arow + mi * 16) * LDK + acol]));
                ldsm4(a1[mi], s2u(&sm[((1 * 2 + st) * BM + arow + mi * 16) * LDK + acol]));
            }
            ldsm4(b0, s2u(&sm[BOFF + ((0 * 2 + st) * BN + brow) * LDK + bcol]));
            ldsm4(b1, s2u(&sm[BOFF + ((1 * 2 + st) * BN + brow) * LDK + bcol]));
#pragma unroll
            for (int mi = 0; mi < 4; mi++)
#pragma unroll
                for (int j = 0; j < 2; j++) {
                    mma16816(acc[mi][j], a0[mi], &b0[j * 2]);
                    mma16816(acc[mi][j], a0[mi], &b1[j * 2]);
                    mma16816(acc[mi][j], a1[mi], &b0[j * 2]);
                }
        }
        __syncthreads();
    }

#pragma unroll
    for (int mi = 0; mi < 4; mi++)
#pragma unroll
        for (int j = 0; j < 2; j++) {
            size_t row = m0 + wm * 64 + mi * 16 + (lane >> 2);
            int col = n0 + wn * 16 + j * 8 + (lane & 3) * 2;
            float* c = acc[mi][j];
#pragma unroll
            for (int half = 0; half < 2; half++) {
                size_t r = row + half * 8;
                float a0v = c[half * 2 + 0] + __ldg(&f1b[col]);
                float a1v = c[half * 2 + 1] + __ldg(&f1b[col + 1]);
                float2 o;
                o.x = 0.5f * a0v * (1.f + erff(a0v * 0.70710678118654752f));
                o.y = 0.5f * a1v * (1.f + erff(a1v * 0.70710678118654752f));
                *reinterpret_cast<float2*>(&g_h1[r * HID + col]) = o;
            }
        }
}

// ---------------- fc2 (R1 verbatim) ----------------
__global__ void fc2_kernel(const float* __restrict__ w, const float* __restrict__ b,
                           float* __restrict__ out) {
    int gwarp = (blockIdx.x * 256 + threadIdx.x) >> 5;
    int lane = threadIdx.x & 31;
    if (gwarp >= NB) return;
    float acc[10];
#pragma unroll
    for (int o = 0; o < 10; o++) acc[o] = 0.f;
    const float* hrow = g_h1 + (size_t)gwarp * HID;
    for (int k = lane; k < HID; k += 32) {
        float h = hrow[k];
#pragma unroll
        for (int o = 0; o < 10; o++) acc[o] += h * w[o * HID + k];
    }
#pragma unroll
    for (int o = 0; o < 10; o++)
#pragma unroll
        for (int off = 16; off; off >>= 1) acc[o] += __shfl_xor_sync(0xffffffffu, acc[o], off);
    if (lane == 0) {
#pragma unroll
        for (int o = 0; o < 10; o++) out[(size_t)gwarp * 10 + o] = acc[o] + b[o];
    }
}

// ---------------- finalize (R1 verbatim) ----------------
__global__ void finalize_kernel(float* __restrict__ out) {
    __shared__ float wsum[8];
    int tid = threadIdx.x;
    float local = 0.f;
    for (int k = tid; k < KMAX; k += 256) {
        float p = (float)g_counts[k] * (1.0f / 131072.0f);
        local += p * logf(p + 1e-10f);
    }
#pragma unroll
    for (int o = 16; o; o >>= 1) local += __shfl_xor_sync(0xffffffffu, local, o);
    if ((tid & 31) == 0) wsum[tid >> 5] = local;
    __syncthreads();
    if (tid == 0) {
        float t = 0.f;
        for (int w = 0; w < 8; w++) t += wsum[w];
        out[20480] = 1.25f * g_lossSum * (1.0f / 33554432.0f);
        out[20481] = expf(-t);
    }
}

// ---------------- launch ----------------
extern "C" void kernel_launch(void* const* d_in, const int* in_sizes, int n_in,
                              void* d_out, int out_size) {
    const float* x    = (const float*)d_in[0];
    const int*   idxp = (const int*)  d_in[1];
    const float* w1   = (const float*)d_in[2];
    const float* b1   = (const float*)d_in[3];
    const float* w2   = (const float*)d_in[4];
    const float* b2   = (const float*)d_in[5];
    const float* cb0  = (const float*)d_in[6];
    const float* cb1  = (const float*)d_in[7];
    const float* cb2  = (const float*)d_in[8];
    const float* f1w  = (const float*)d_in[9];
    const float* f1b  = (const float*)d_in[10];
    const float* f2w  = (const float*)d_in[11];
    const float* f2b  = (const float*)d_in[12];
    float* out = (float*)d_out;

    constexpr int SMC = (2 * 32 * 68 + 2 * 32 * 264) * 4;        // 84992
    constexpr int SMT = 256 * 65 * 4;                             // 66560
    constexpr int SMS = (2 * 2 * 128 + 2 * 2 * 128) * 40 * 2;     // 81920
    constexpr int SMF = (2 * 2 * 128 + 2 * 2 * 64)  * 40 * 2;     // 61440
    cudaFuncSetAttribute(conv2_gemm_kernel, cudaFuncAttributeMaxDynamicSharedMemorySize, SMC);
    cudaFuncSetAttribute(feasplit_kernel,   cudaFuncAttributeMaxDynamicSharedMemorySize, SMT);
    cudaFuncSetAttribute(scores_kernel,     cudaFuncAttributeMaxDynamicSharedMemorySize, SMS);
    cudaFuncSetAttribute(fc1_tc_kernel,     cudaFuncAttributeMaxDynamicSharedMemorySize, SMF);

    zero_stats_kernel<<<1, 1024>>>();
    prep_f1w_kernel<<<32768, 256>>>(f1w);
    prep_w2p_kernel<<<2048, 256>>>(w2);
    prep_codes_kernel<<<1024, 256>>>(cb0, cb1, cb2, idxp);
    conv1_kernel<<<NB, 256>>>(x, w1, b1);
    im2col_kernel<<<dim3(16, NB), 256>>>();
    conv2_gemm_kernel<<<NB, 256, SMC>>>(b2);
    feasplit_kernel<<<NB, 256, SMT>>>();
    scores_kernel<<<dim3(8, 1024), 256, SMS>>>();
    argmax_refine_kernel<<<NROWS / 8, 256>>>();
    gather_kernel<<<NB, 256>>>(cb0, cb1, cb2, idxp);
    fc1_tc_kernel<<<dim3(8, 16), 256, SMF>>>(f1b);
    fc2_kernel<<<NB / 8, 256>>>(f2w, f2b, out);
    finalize_kernel<<<1, 256>>>(out);
}